// round 8
// baseline (speedup 1.0000x reference)
#include <cuda_runtime.h>
#include <cstdint>
#include <math.h>

// ---------------------------------------------------------------------------
// Problem dims (fixed by dataset)
// ---------------------------------------------------------------------------
#define T_TOK 32768          // B*S tokens
#define H_DIM 768
#define I_DIM 3072
#define E_NUM 8
#define TP    (T_TOK * 2)    // total (token, expert-slot) rows, top-2
#define MAX_TILES 520

// GEMM tiling (legacy mma.sync m16n8k8 tf32; tcgen05 unavailable: harness
// ptxas targets plain sm_103 which rejects all 'a'-feature instructions)
// BN=128, 2 CTAs/SM. Inner loop uses explicit fragment double-buffering so
// the LDSM chain of step kk+1 overlaps the MMAs of step kk.
#define BM 128
#define BN 128
#define BK 32
#define ROWF 36                    // smem row stride in floats (144B): LDSM + cp.async conflict-free
#define A_ST (BM * ROWF)           // 4608 floats
#define B_ST (BN * ROWF)           // 4608 floats
#define STG_F (A_ST + B_ST)        // 9216 floats = 36864 B per stage
#define NSTAGE 3
#define GEMM_SMEM (STG_F * NSTAGE * 4)   // 110592 B -> 2 CTAs/SM

// ---------------------------------------------------------------------------
// Scratch (device globals; no allocation allowed)
// ---------------------------------------------------------------------------
__device__ float g_xr[(size_t)T_TOK * H_DIM];            // tf32-rounded x
__device__ float g_w1t[(size_t)E_NUM * I_DIM * H_DIM];   // [E][I][H] (w1^T, tf32-rounded)
__device__ float g_w2t[(size_t)E_NUM * H_DIM * I_DIM];   // [E][H][I] (w2^T, tf32-rounded)
__device__ float g_hmid[(size_t)TP * I_DIM];             // gelu(x@w1+b1), permuted, tf32-rounded
__device__ float g_y[(size_t)TP * H_DIM];                // hmid@w2+b2, permuted rows
__device__ int   g_permIdx[TP];
__device__ int   g_slotPos[TP];
__device__ float g_wts[TP];
__device__ int   g_sel[TP];
__device__ int   g_counts[E_NUM];
__device__ int   g_cursor[E_NUM];
__device__ int   g_tileE[MAX_TILES];
__device__ int   g_tileRow[MAX_TILES];
__device__ int   g_tileEnd[MAX_TILES];

// ---------------------------------------------------------------------------
// Helpers
// ---------------------------------------------------------------------------
__device__ __forceinline__ uint32_t smem_u32(const void* p) {
    uint32_t a;
    asm("{ .reg .u64 t; cvta.to.shared.u64 t, %1; cvt.u32.u64 %0, t; }" : "=r"(a) : "l"(p));
    return a;
}
__device__ __forceinline__ float to_tf32(float f) {
    float r; asm("cvt.rna.tf32.f32 %0, %1;" : "=f"(r) : "f"(f)); return r;
}
__device__ __forceinline__ float4 tf32x4(float4 v) {
    v.x = to_tf32(v.x); v.y = to_tf32(v.y); v.z = to_tf32(v.z); v.w = to_tf32(v.w);
    return v;
}
__device__ __forceinline__ float gelu_exact(float v) {
    return 0.5f * v * (1.0f + erff(v * 0.7071067811865476f));
}
__device__ __forceinline__ void cp16(uint32_t dst, const void* src) {
    asm volatile("cp.async.cg.shared.global [%0], [%1], 16;" :: "r"(dst), "l"(src));
}
__device__ __forceinline__ void mma_tf32(float* c, const uint32_t* a, const uint32_t* b) {
    asm volatile(
        "mma.sync.aligned.m16n8k8.row.col.f32.tf32.tf32.f32 "
        "{%0,%1,%2,%3}, {%4,%5,%6,%7}, {%8,%9}, {%0,%1,%2,%3};"
        : "+f"(c[0]), "+f"(c[1]), "+f"(c[2]), "+f"(c[3])
        : "r"(a[0]), "r"(a[1]), "r"(a[2]), "r"(a[3]), "r"(b[0]), "r"(b[1]));
}
// ldmatrix x4: pure 8x8x2B tile movement; with tf32 data the thread->element
// mapping reproduces the m16n8k8 A/B fragment layout exactly.
__device__ __forceinline__ void ldsm4(uint32_t* d, uint32_t addr) {
    asm volatile("ldmatrix.sync.aligned.m8n8.x4.shared.b16 {%0,%1,%2,%3}, [%4];"
        : "=r"(d[0]), "=r"(d[1]), "=r"(d[2]), "=r"(d[3]) : "r"(addr));
}

// ---------------------------------------------------------------------------
// Kernel 0 (launch idx 0): router — logits, top-2, weights, counts; also
// writes tf32-rounded x (fused rounding pass).
// ---------------------------------------------------------------------------
__global__ void router_kernel(const float* __restrict__ x, const float* __restrict__ gw,
                              float* __restrict__ logits_out) {
    __shared__ float4 sg[E_NUM * 192];
    int tid = threadIdx.x;
    for (int i = tid; i < E_NUM * 192; i += 256) sg[i] = ((const float4*)gw)[i];
    __syncthreads();

    int warp = tid >> 5, lane = tid & 31;
    int t = blockIdx.x * 8 + warp;
    const float4* xr = (const float4*)(x + (size_t)t * H_DIM);
    float4* xo = (float4*)(g_xr + (size_t)t * H_DIM);

    float acc[E_NUM];
#pragma unroll
    for (int e = 0; e < E_NUM; e++) acc[e] = 0.f;

    for (int j = lane; j < 192; j += 32) {
        float4 xv = xr[j];
        xo[j] = tf32x4(xv);          // fused tf32 rounding (RN, unbiased)
#pragma unroll
        for (int e = 0; e < E_NUM; e++) {
            float4 g = sg[e * 192 + j];
            acc[e] += xv.x * g.x + xv.y * g.y + xv.z * g.z + xv.w * g.w;
        }
    }
#pragma unroll
    for (int off = 16; off > 0; off >>= 1)
#pragma unroll
        for (int e = 0; e < E_NUM; e++)
            acc[e] += __shfl_xor_sync(0xffffffffu, acc[e], off);

    if (lane == 0) {
        int i0 = 0; float l0 = acc[0];
#pragma unroll
        for (int e = 1; e < E_NUM; e++) if (acc[e] > l0) { l0 = acc[e]; i0 = e; }
        int i1 = -1; float l1 = -3.4e38f;
#pragma unroll
        for (int e = 0; e < E_NUM; e++)
            if (e != i0 && acc[e] > l1) { l1 = acc[e]; i1 = e; }
        float p1 = __expf(l1 - l0);
        float inv = 1.0f / (1.0f + p1);
        g_sel[2 * t] = i0;  g_sel[2 * t + 1] = i1;
        g_wts[2 * t] = inv; g_wts[2 * t + 1] = p1 * inv;
        atomicAdd(&g_counts[i0], 1);
        atomicAdd(&g_counts[i1], 1);
        float* lo = logits_out + (size_t)t * E_NUM;
#pragma unroll
        for (int e = 0; e < E_NUM; e++) lo[e] = acc[e];
    }
}

// ---------------------------------------------------------------------------
// Kernel 1: plan — scan counts, set cursors, build ragged tile table
// ---------------------------------------------------------------------------
__global__ void plan_kernel() {
    if (threadIdx.x != 0 || blockIdx.x != 0) return;
    int s = 0, idx = 0;
    for (int e = 0; e < E_NUM; e++) {
        int c = g_counts[e];
        g_cursor[e] = s;
        int en = s + c;
        for (int r = s; r < en; r += BM) {
            g_tileE[idx] = e; g_tileRow[idx] = r; g_tileEnd[idx] = en; idx++;
        }
        s = en;
    }
    for (; idx < MAX_TILES; idx++) g_tileE[idx] = -1;
}

// ---------------------------------------------------------------------------
// Kernel 2: prep — fused scatter + both weight transposes.
// z < 16: transpose slab (z<8: w1[e=z]; z>=8: w2[e=z-8]).
// z == 16: scatter, block id linearized over the x*y plane.
// ---------------------------------------------------------------------------
__global__ void prep_kernel(const float* __restrict__ w1, const float* __restrict__ w2) {
    int z = blockIdx.z;
    int tx = threadIdx.x, ty = threadIdx.y;
    if (z < 16) {
        __shared__ float tile[32][33];
        int which = z >> 3, e = z & 7;
        const float* src = which ? w2 : w1;
        float* dst = which ? g_w2t : g_w1t;
        int R = which ? I_DIM : H_DIM;
        int C = which ? H_DIM : I_DIM;
        int c0 = (which ? blockIdx.y : blockIdx.x) * 32;
        int r0 = (which ? blockIdx.x : blockIdx.y) * 32;
        const float* s = src + (size_t)e * R * C;
        float* d = dst + (size_t)e * C * R;
#pragma unroll
        for (int j = 0; j < 32; j += 8)
            tile[ty + j][tx] = s[(size_t)(r0 + ty + j) * C + (c0 + tx)];
        __syncthreads();
#pragma unroll
        for (int j = 0; j < 32; j += 8)
            d[(size_t)(c0 + ty + j) * R + (r0 + tx)] = to_tf32(tile[tx][ty + j]);
    } else {
        int bid = blockIdx.y * gridDim.x + blockIdx.x;   // linearized (R6 fix)
        if (bid >= T_TOK / 256) return;
        int t = bid * 256 + ty * 32 + tx;
#pragma unroll
        for (int k = 0; k < 2; k++) {
            int e = g_sel[2 * t + k];
            int pos = atomicAdd(&g_cursor[e], 1);
            g_permIdx[pos] = t;
            g_slotPos[2 * t + k] = pos;
        }
    }
}

// ---------------------------------------------------------------------------
// Kernel 3: grouped GEMM, mma.sync tf32, CTA 128x128, 8 warps (64x32 each),
// 3-stage cp.async pipeline, 2 CTAs/SM, REGISTER-LEVEL FRAGMENT DOUBLE
// BUFFERING: LDSMs for kk+1 issue before the MMAs of kk, so the warp stalls
// on shared-load latency at most once per K-iteration instead of per kk.
//   mode 0: hmid[p] = tf32(gelu(xr[perm[p]] @ w1t^T + b1))   K=768,  NTOT=3072
//   mode 1: y[p]    = hmid[p] @ w2t^T + b2                   K=3072, NTOT=768
// ---------------------------------------------------------------------------
__global__ void __launch_bounds__(256, 2)
moe_gemm(int mode, const float* __restrict__ bias_all) {
    int tile = blockIdx.y;
    int e = g_tileE[tile];
    if (e < 0) return;

    const int K    = mode ? I_DIM : H_DIM;
    const int NTOT = mode ? H_DIM : I_DIM;
    const int NK   = K / BK;
    const int n0   = blockIdx.x * BN;
    const int rowStart = g_tileRow[tile];
    const int rowEnd   = g_tileEnd[tile];

    extern __shared__ float sm[];
    __shared__ int   s_row[BM];
    __shared__ float s_bias[BN];

    const int tid = threadIdx.x;
    const int wid = tid >> 5, lane = tid & 31;
    const int wm = wid >> 2, wn = wid & 3;       // warp grid 2 x 4, warp tile 64x32
    const int g = lane >> 2, tig = lane & 3;

    const float* Asrc = mode ? g_hmid : g_xr;
    const float* Bsrc = (mode ? g_w2t : g_w1t) + ((size_t)e * NTOT + n0) * K;

    if (tid < BM) {
        int r = rowStart + tid;
        int rr = (r < rowEnd) ? r : rowStart;     // clamp loads; stores predicated later
        s_row[tid] = mode ? rr : g_permIdx[rr];
    }
    if (tid < BN) s_bias[tid] = bias_all[(size_t)e * NTOT + n0 + tid];
    __syncthreads();

    // cp.async load assignment: 2 threads per row (A and B both 128 rows)
    const int ar = tid >> 1, ah = tid & 1;
    const float* aRow = Asrc + (size_t)s_row[ar] * K + ah * 16;
    const float* bRow = Bsrc + (size_t)ar * K + ah * 16;
    const uint32_t aDst0 = smem_u32(sm + ar * ROWF + ah * 16);
    const uint32_t bDst0 = smem_u32(sm + A_ST + ar * ROWF + ah * 16);

    // ldmatrix per-thread addresses (byte offsets within a stage).
    const int q = lane >> 3, r8 = lane & 7;
    const uint32_t aFragBase =
        (uint32_t)(((wm * 64 + (q & 1) * 8 + r8) * ROWF + (q >> 1) * 4) * 4);
    const uint32_t bFragBase =
        (uint32_t)(((wn * 32 + (q >> 1) * 8 + r8) * ROWF + (q & 1) * 4) * 4);
    const uint32_t suA = smem_u32(sm);
    const uint32_t suB = smem_u32(sm + A_ST);

#define LOAD_STAGE(ks)                                                         \
    do {                                                                       \
        int _k0 = (ks) * BK;                                                   \
        uint32_t _soff = ((ks) % NSTAGE) * (STG_F * 4);                        \
        const float* _ap = aRow + _k0;                                         \
        const float* _bp = bRow + _k0;                                         \
        _Pragma("unroll")                                                      \
        for (int j = 0; j < 4; j++) cp16(aDst0 + _soff + j * 16, _ap + j * 4); \
        _Pragma("unroll")                                                      \
        for (int j = 0; j < 4; j++) cp16(bDst0 + _soff + j * 16, _bp + j * 4); \
        asm volatile("cp.async.commit_group;" ::: "memory");                   \
    } while (0)

// load fragment buffer `buf` with k-chunk kk from stage base (sa, sb)
#define LDFRAG(buf, sa, sb, kk)                                                \
    do {                                                                       \
        _Pragma("unroll")                                                      \
        for (int _mt = 0; _mt < 4; _mt++)                                      \
            ldsm4(af[buf][_mt], (sa) + (uint32_t)(_mt * 16 * ROWF * 4 + (kk) * 32)); \
        _Pragma("unroll")                                                      \
        for (int _np = 0; _np < 2; _np++)                                      \
            ldsm4(bf[buf][_np], (sb) + (uint32_t)(_np * 16 * ROWF * 4 + (kk) * 32)); \
    } while (0)

    float acc[4][4][4];
#pragma unroll
    for (int mt = 0; mt < 4; mt++)
#pragma unroll
        for (int nt = 0; nt < 4; nt++)
#pragma unroll
            for (int j = 0; j < 4; j++) acc[mt][nt][j] = 0.f;

    uint32_t af[2][4][4], bf[2][2][4];   // double-buffered fragments

    LOAD_STAGE(0);
    LOAD_STAGE(1);

    for (int ks = 0; ks < NK; ks++) {
        if (ks < NK - 2) asm volatile("cp.async.wait_group 1;" ::: "memory");
        else             asm volatile("cp.async.wait_group 0;" ::: "memory");
        __syncthreads();
        if (ks + 2 < NK) LOAD_STAGE(ks + 2);   // overwrites stage ks-1 (consumed+synced)

        const uint32_t stg = (uint32_t)((ks % NSTAGE) * (STG_F * 4));
        const uint32_t sa = suA + stg + aFragBase;
        const uint32_t sb = suB + stg + bFragBase;

        LDFRAG(0, sa, sb, 0);
#pragma unroll
        for (int kk = 0; kk < 4; kk++) {
            if (kk < 3) LDFRAG((kk + 1) & 1, sa, sb, kk + 1);  // prefetch next chunk
            const int cb = kk & 1;
#pragma unroll
            for (int mt = 0; mt < 4; mt++)
#pragma unroll
                for (int nt = 0; nt < 4; nt++)
                    mma_tf32(acc[mt][nt], af[cb][mt], &bf[cb][nt >> 1][(nt & 1) * 2]);
        }
    }

    // Epilogue: bias (+ gelu + tf32-round for mode 0), predicated row stores
    float* Dst = mode ? g_y : g_hmid;
#pragma unroll
    for (int mt = 0; mt < 4; mt++) {
#pragma unroll
        for (int i = 0; i < 2; i++) {
            int r = rowStart + wm * 64 + mt * 16 + g + i * 8;
            if (r >= rowEnd) continue;
            float* drow = Dst + (size_t)r * NTOT + n0;
#pragma unroll
            for (int nt = 0; nt < 4; nt++) {
                int c = wn * 32 + nt * 8 + tig * 2;
                float v0 = acc[mt][nt][i * 2 + 0] + s_bias[c];
                float v1 = acc[mt][nt][i * 2 + 1] + s_bias[c + 1];
                if (mode == 0) {
                    v0 = to_tf32(gelu_exact(v0));
                    v1 = to_tf32(gelu_exact(v1));
                }
                *(float2*)(drow + c) = make_float2(v0, v1);
            }
        }
    }
#undef LOAD_STAGE
#undef LDFRAG
}

// ---------------------------------------------------------------------------
// Kernel 5: combine — out[t] = w0*y[pos0] + w1*y[pos1]
// ---------------------------------------------------------------------------
__global__ void combine_kernel(float* __restrict__ out) {
    int t = blockIdx.x;
    int p0 = g_slotPos[2 * t], p1 = g_slotPos[2 * t + 1];
    float w0 = g_wts[2 * t], w1 = g_wts[2 * t + 1];
    const float4* y0 = (const float4*)(g_y + (size_t)p0 * H_DIM);
    const float4* y1 = (const float4*)(g_y + (size_t)p1 * H_DIM);
    float4* o = (float4*)(out + (size_t)t * H_DIM);
    int i = threadIdx.x;
    float4 a = y0[i], b = y1[i];
    o[i] = make_float4(w0 * a.x + w1 * b.x, w0 * a.y + w1 * b.y,
                       w0 * a.z + w1 * b.z, w0 * a.w + w1 * b.w);
}

// ---------------------------------------------------------------------------
// Launch — moe_gemm(0) is KERNEL launch index 3 (counts zeroed via memset
// node, which is not a kernel launch), targeting the ncu capture window.
// ---------------------------------------------------------------------------
extern "C" void kernel_launch(void* const* d_in, const int* in_sizes, int n_in,
                              void* d_out, int out_size) {
    const float* x  = (const float*)d_in[0];  // hidden_states [B,S,H]
    const float* gw = (const float*)d_in[1];  // gate_w [E,H]
    const float* w1 = (const float*)d_in[2];  // [E,H,I]
    const float* b1 = (const float*)d_in[3];  // [E,I]
    const float* w2 = (const float*)d_in[4];  // [E,I,H]
    const float* b2 = (const float*)d_in[5];  // [E,H]
    float* out = (float*)d_out;
    float* logits = out + ((size_t)out_size - (size_t)T_TOK * E_NUM);

    cudaFuncSetAttribute(moe_gemm, cudaFuncAttributeMaxDynamicSharedMemorySize, GEMM_SMEM);

    void* countsPtr = nullptr;
    cudaGetSymbolAddress(&countsPtr, g_counts);
    cudaMemsetAsync(countsPtr, 0, E_NUM * sizeof(int));         // memset node

    router_kernel<<<T_TOK / 8, 256>>>(x, gw, logits);           // k0
    plan_kernel<<<1, 32>>>();                                   // k1
    prep_kernel<<<dim3(96, 24, 17), dim3(32, 8)>>>(w1, w2);     // k2 (scatter+transpose)
    moe_gemm<<<dim3(I_DIM / BN, MAX_TILES), 256, GEMM_SMEM>>>(0, b1);  // k3 <- profiled
    moe_gemm<<<dim3(H_DIM / BN, MAX_TILES), 256, GEMM_SMEM>>>(1, b2);  // k4
    combine_kernel<<<T_TOK, 192>>>(out);                        // k5
}

// round 13
// speedup vs baseline: 1.4739x; 1.4739x over previous
#include <cuda_runtime.h>
#include <cstdint>
#include <math.h>

// ---------------------------------------------------------------------------
// Problem dims (fixed by dataset)
// ---------------------------------------------------------------------------
#define T_TOK 32768          // B*S tokens
#define H_DIM 768
#define I_DIM 3072
#define E_NUM 8
#define TP    (T_TOK * 2)    // total (token, expert-slot) rows, top-2
#define TROWS (TP + 1024)    // permuted row space, expert starts 128-aligned
#define MAX_TILES 520

// GEMM tiling (legacy mma.sync m16n8k8 tf32; tcgen05 unavailable: harness
// ptxas targets plain sm_103). Streamed operands live in gmem as contiguous
// pre-swizzled 128x32 tiles so each stage is ONE cp.async.bulk (UBLKCP) of
// 16 KB instead of 1024 LDGSTS — removing the dominant issue-bandwidth cost.
#define BM 128
#define BN 128
#define BK 32
#define TILE_F 4096                     // floats per 128x32 tile (16 KB)
#define STG_BYTES 32768                 // A tile + B tile per stage
#define NSTAGE 3
#define GEMM_SMEM (STG_BYTES * NSTAGE)  // 98304 B -> 2 CTAs/SM

// ---------------------------------------------------------------------------
// Scratch (device globals; no allocation allowed)
// ---------------------------------------------------------------------------
__device__ float g_xr[(size_t)T_TOK * H_DIM];              // tf32-rounded x (row-major)
__device__ float g_w1t[(size_t)E_NUM * 24 * 24 * TILE_F];  // w1^T tiled [e][nt][ks][tile]
__device__ float g_w2t[(size_t)E_NUM * 6 * 96 * TILE_F];   // w2^T tiled [e][nt][ks][tile]
__device__ float g_hmid[(size_t)96 * TROWS * 32];          // gelu out, k-chunk tiled [ks][p][32]
__device__ float g_y[(size_t)TROWS * H_DIM];               // hmid@w2+b2, permuted rows
__device__ int   g_permIdx[TROWS];
__device__ int   g_slotPos[TP];
__device__ float g_wts[TP];
__device__ int   g_sel[TP];
__device__ int   g_counts[E_NUM];
__device__ int   g_cursor[E_NUM];
__device__ int   g_tileE[MAX_TILES];
__device__ int   g_tileRow[MAX_TILES];
__device__ int   g_tileEnd[MAX_TILES];

// ---------------------------------------------------------------------------
// Helpers
// ---------------------------------------------------------------------------
__device__ __forceinline__ uint32_t smem_u32(const void* p) {
    uint32_t a;
    asm("{ .reg .u64 t; cvta.to.shared.u64 t, %1; cvt.u32.u64 %0, t; }" : "=r"(a) : "l"(p));
    return a;
}
__device__ __forceinline__ float to_tf32(float f) {
    float r; asm("cvt.rna.tf32.f32 %0, %1;" : "=f"(r) : "f"(f)); return r;
}
__device__ __forceinline__ float4 tf32x4(float4 v) {
    v.x = to_tf32(v.x); v.y = to_tf32(v.y); v.z = to_tf32(v.z); v.w = to_tf32(v.w);
    return v;
}
__device__ __forceinline__ float gelu_exact(float v) {
    return 0.5f * v * (1.0f + erff(v * 0.7071067811865476f));
}
// float index inside a swizzled 128-row x 32-float tile (XOR of 16B lanes);
// row is TILE-LOCAL (expert starts are 128-aligned so global r&7 == local&7)
__device__ __forceinline__ int swz(int row, int c) {
    return row * 32 + ((((c >> 2) ^ (row & 7)) << 2) | (c & 3));
}
__device__ __forceinline__ void cp16(uint32_t dst, const void* src) {
    asm volatile("cp.async.cg.shared.global [%0], [%1], 16;" :: "r"(dst), "l"(src));
}
__device__ __forceinline__ void bulk_g2s(uint32_t dst, const void* src, uint32_t bytes,
                                         uint32_t mbar) {
    asm volatile(
        "cp.async.bulk.shared::cluster.global.mbarrier::complete_tx::bytes "
        "[%0], [%1], %2, [%3];"
        :: "r"(dst), "l"(src), "r"(bytes), "r"(mbar) : "memory");
}
#define FENCE_PROXY_ASYNC() asm volatile("fence.proxy.async.shared::cta;" ::: "memory")
#define MBARRIER_INIT(addr, cnt) \
    asm volatile("mbarrier.init.shared.b64 [%0], %1;" :: "r"((uint32_t)(addr)), "r"((uint32_t)(cnt)) : "memory")
#define MBARRIER_EXPECT_TX(addr, tx) \
    asm volatile("mbarrier.arrive.expect_tx.shared.b64 _, [%0], %1;" :: "r"((uint32_t)(addr)), "r"((uint32_t)(tx)) : "memory")
#define MBARRIER_WAIT_PARITY(addr, par) do {                                              \
    uint32_t _m = (uint32_t)(addr), _p = (uint32_t)(par), _d;                             \
    asm volatile("{\n\t.reg .pred p;\n\t"                                                 \
        "mbarrier.try_wait.parity.acquire.cta.shared::cta.b64 p, [%1], %2;\n\t"           \
        "selp.b32 %0, 1, 0, p;\n\t}" : "=r"(_d) : "r"(_m), "r"(_p) : "memory");           \
    if (!_d) {                                                                            \
        asm volatile("{\n\t.reg .pred P1;\n\t"                                            \
            "WL_%=:\n\t"                                                                  \
            "mbarrier.try_wait.parity.acquire.cta.shared::cta.b64 P1, [%0], %1, 0x989680;\n\t" \
            "@P1 bra.uni WD_%=;\n\t"                                                      \
            "bra.uni WL_%=;\n\t"                                                          \
            "WD_%=:\n\t}" :: "r"(_m), "r"(_p) : "memory");                                \
    }                                                                                     \
} while (0)
__device__ __forceinline__ void mma_tf32(float* c, const uint32_t* a, const uint32_t* b) {
    asm volatile(
        "mma.sync.aligned.m16n8k8.row.col.f32.tf32.tf32.f32 "
        "{%0,%1,%2,%3}, {%4,%5,%6,%7}, {%8,%9}, {%0,%1,%2,%3};"
        : "+f"(c[0]), "+f"(c[1]), "+f"(c[2]), "+f"(c[3])
        : "r"(a[0]), "r"(a[1]), "r"(a[2]), "r"(a[3]), "r"(b[0]), "r"(b[1]));
}
__device__ __forceinline__ void ldsm4(uint32_t* d, uint32_t addr) {
    asm volatile("ldmatrix.sync.aligned.m8n8.x4.shared.b16 {%0,%1,%2,%3}, [%4];"
        : "=r"(d[0]), "=r"(d[1]), "=r"(d[2]), "=r"(d[3]) : "r"(addr));
}

// ---------------------------------------------------------------------------
// Kernel 0: router — logits, top-2, weights, counts; writes tf32-rounded x
// ---------------------------------------------------------------------------
__global__ void router_kernel(const float* __restrict__ x, const float* __restrict__ gw,
                              float* __restrict__ logits_out) {
    __shared__ float4 sg[E_NUM * 192];
    int tid = threadIdx.x;
    for (int i = tid; i < E_NUM * 192; i += 256) sg[i] = ((const float4*)gw)[i];
    __syncthreads();

    int warp = tid >> 5, lane = tid & 31;
    int t = blockIdx.x * 8 + warp;
    const float4* xr = (const float4*)(x + (size_t)t * H_DIM);
    float4* xo = (float4*)(g_xr + (size_t)t * H_DIM);

    float acc[E_NUM];
#pragma unroll
    for (int e = 0; e < E_NUM; e++) acc[e] = 0.f;

    for (int j = lane; j < 192; j += 32) {
        float4 xv = xr[j];
        xo[j] = tf32x4(xv);
#pragma unroll
        for (int e = 0; e < E_NUM; e++) {
            float4 g = sg[e * 192 + j];
            acc[e] += xv.x * g.x + xv.y * g.y + xv.z * g.z + xv.w * g.w;
        }
    }
#pragma unroll
    for (int off = 16; off > 0; off >>= 1)
#pragma unroll
        for (int e = 0; e < E_NUM; e++)
            acc[e] += __shfl_xor_sync(0xffffffffu, acc[e], off);

    if (lane == 0) {
        int i0 = 0; float l0 = acc[0];
#pragma unroll
        for (int e = 1; e < E_NUM; e++) if (acc[e] > l0) { l0 = acc[e]; i0 = e; }
        int i1 = -1; float l1 = -3.4e38f;
#pragma unroll
        for (int e = 0; e < E_NUM; e++)
            if (e != i0 && acc[e] > l1) { l1 = acc[e]; i1 = e; }
        float p1 = __expf(l1 - l0);
        float inv = 1.0f / (1.0f + p1);
        g_sel[2 * t] = i0;  g_sel[2 * t + 1] = i1;
        g_wts[2 * t] = inv; g_wts[2 * t + 1] = p1 * inv;
        atomicAdd(&g_counts[i0], 1);
        atomicAdd(&g_counts[i1], 1);
        float* lo = logits_out + (size_t)t * E_NUM;
#pragma unroll
        for (int e = 0; e < E_NUM; e++) lo[e] = acc[e];
    }
}

// ---------------------------------------------------------------------------
// Kernel 1: plan — expert starts ALIGNED to 128 (swizzle-phase + bulk-align)
// ---------------------------------------------------------------------------
__global__ void plan_kernel() {
    if (threadIdx.x != 0 || blockIdx.x != 0) return;
    int s = 0, idx = 0;
    for (int e = 0; e < E_NUM; e++) {
        int c = g_counts[e];
        g_cursor[e] = s;
        int en = s + c;
        for (int r = s; r < en; r += BM) {
            g_tileE[idx] = e; g_tileRow[idx] = r; g_tileEnd[idx] = en; idx++;
        }
        s = (en + 127) & ~127;      // 128-align next expert's segment
    }
    for (; idx < MAX_TILES; idx++) g_tileE[idx] = -1;
}

// ---------------------------------------------------------------------------
// Kernel 2: prep — scatter + both weight transposes into TILED+SWIZZLED
// layout: w1t block (e, nt<24, ks<24), w2t block (e, nt<6, ks<96),
// each block = contiguous 16 KB 128x32 tile ready for cp.async.bulk.
// ---------------------------------------------------------------------------
__global__ void prep_kernel(const float* __restrict__ w1, const float* __restrict__ w2) {
    int z = blockIdx.z;
    int tx = threadIdx.x, ty = threadIdx.y;
    if (z < 16) {
        __shared__ float tile[32][33];
        int which = z >> 3, e = z & 7;
        const float* src = which ? w2 : w1;
        float* dst = which ? g_w2t : g_w1t;
        int R = which ? I_DIM : H_DIM;       // k-dim
        int C = which ? H_DIM : I_DIM;       // n-dim
        int c0 = (which ? blockIdx.y : blockIdx.x) * 32;   // n block
        int r0 = (which ? blockIdx.x : blockIdx.y) * 32;   // k block
        const float* s = src + (size_t)e * R * C;
#pragma unroll
        for (int j = 0; j < 32; j += 8)
            tile[ty + j][tx] = s[(size_t)(r0 + ty + j) * C + (c0 + tx)];
        __syncthreads();
        int ks = r0 >> 5;                    // whole 32-block -> single k-chunk
#pragma unroll
        for (int j = 0; j < 32; j += 8) {
            int n = c0 + ty + j;
            int k = r0 + tx;
            int nt = n >> 7, row = n & 127, c = k & 31;
            size_t base = which ? ((((size_t)e * 6 + nt) * 96 + ks) << 12)
                                : ((((size_t)e * 24 + nt) * 24 + ks) << 12);
            dst[base + swz(row, c)] = to_tf32(tile[tx][ty + j]);
        }
    } else {
        int bid = blockIdx.y * gridDim.x + blockIdx.x;   // linearized
        if (bid >= T_TOK / 256) return;
        int t = bid * 256 + ty * 32 + tx;
#pragma unroll
        for (int k = 0; k < 2; k++) {
            int e = g_sel[2 * t + k];
            int pos = atomicAdd(&g_cursor[e], 1);
            g_permIdx[pos] = t;
            g_slotPos[2 * t + k] = pos;
        }
    }
}

// ---------------------------------------------------------------------------
// Kernel 3: grouped GEMM, mma.sync tf32, CTA 128x128, 8 warps (64x32),
// 3-stage pipeline, 2 CTAs/SM.
//  Per-iteration order: wait(stage ks) -> __syncthreads -> issue(ks+2) ->
//  consume(ks). The barrier AFTER the waits closes the ks=0 visibility race
//  (a thread could previously ldmatrix rows whose cp.async was issued by a
//  different thread and had not landed).
//   mode 0: hmid[p] = tf32(gelu(xr[perm[p]] @ w1t^T + b1))   K=768,  NTOT=3072
//   mode 1: y[p]    = hmid[p] @ w2t^T + b2                   K=3072, NTOT=768
// ---------------------------------------------------------------------------
__global__ void __launch_bounds__(256, 2)
moe_gemm(int mode, const float* __restrict__ bias_all) {
    int tile = blockIdx.y;
    int e = g_tileE[tile];
    if (e < 0) return;

    const int K    = mode ? I_DIM : H_DIM;
    const int NTOT = mode ? H_DIM : I_DIM;
    const int NK   = K / BK;
    const int nt   = blockIdx.x;
    const int n0   = nt * BN;
    const int rowStart = g_tileRow[tile];   // multiple of 128 (aligned plan)
    const int rowEnd   = g_tileEnd[tile];

    extern __shared__ float sm[];
    __shared__ int   s_row[BM];
    __shared__ float s_bias[BN];
    __shared__ __align__(8) uint64_t s_mbar[NSTAGE];

    const int tid = threadIdx.x;
    const int wid = tid >> 5, lane = tid & 31;
    const int wm = wid >> 2, wn = wid & 3;       // warp grid 2 x 4, warp tile 64x32
    const int g = lane >> 2, tig = lane & 3;
    const int q = lane >> 3, r8 = lane & 7;
    const int qh = q >> 1, ql = q & 1;

    // B tile stream base (floats): tiled blocks [e][nt][ks]
    const float* bTile = mode ? (g_w2t + ((((size_t)e * 6 + nt) * 96) << 12))
                              : (g_w1t + ((((size_t)e * 24 + nt) * 24) << 12));
    // A bulk stream (mode 1): k-chunk tiled hmid, rows rowStart..rowStart+127
    const float* aBulk = g_hmid + (size_t)rowStart * 32;

    if (tid == 0) {
#pragma unroll
        for (int s = 0; s < NSTAGE; s++) MBARRIER_INIT(smem_u32(&s_mbar[s]), 1);
        FENCE_PROXY_ASYNC();                  // order init before async-proxy use
    }
    if (!mode && tid < BM) {
        int r = rowStart + tid;
        int rr = (r < rowEnd) ? r : rowStart;     // clamp loads; stores predicated later
        s_row[tid] = g_permIdx[rr];
    }
    if (tid < BN) s_bias[tid] = bias_all[(size_t)e * NTOT + n0 + tid];
    __syncthreads();

    const uint32_t suA = smem_u32(sm);
    uint32_t mb[NSTAGE];
#pragma unroll
    for (int s = 0; s < NSTAGE; s++) mb[s] = smem_u32(&s_mbar[s]);

    // mode-0 A gather: 2 threads per row, 64 B each
    const int ar = tid >> 1, ah = tid & 1;
    const float* aRow = mode ? (const float*)nullptr
                             : g_xr + (size_t)s_row[ar] * H_DIM + ah * 16;
    const uint32_t aDstRow = suA + (uint32_t)(ar * 128);

#define ISSUE_STAGE(ks)                                                        \
    do {                                                                       \
        int _s = (ks) % NSTAGE;                                                \
        uint32_t _sb = (uint32_t)(_s * STG_BYTES);                             \
        if (tid == 0) {                                                        \
            MBARRIER_EXPECT_TX(mb[_s], mode ? 32768u : 16384u);                \
            bulk_g2s(suA + _sb + 16384, bTile + ((size_t)(ks) << 12), 16384, mb[_s]); \
            if (mode) bulk_g2s(suA + _sb, aBulk + (size_t)(ks) * (TROWS * 32), \
                               16384, mb[_s]);                                 \
        }                                                                      \
        if (!mode) {                                                           \
            const float* _ap = aRow + (ks) * BK;                               \
            _Pragma("unroll")                                                  \
            for (int j = 0; j < 4; j++)                                        \
                cp16(aDstRow + _sb + ((uint32_t)(((ah * 4 + j) ^ (ar & 7)) << 4)), \
                     _ap + j * 4);                                             \
            asm volatile("cp.async.commit_group;" ::: "memory");               \
        }                                                                      \
    } while (0)

    // ldmatrix row offsets (bytes within a tile)
    uint32_t aOff[4], bOff[2];
#pragma unroll
    for (int mt = 0; mt < 4; mt++)
        aOff[mt] = (uint32_t)((wm * 64 + mt * 16 + ql * 8 + r8) * 128);
#pragma unroll
    for (int np = 0; np < 2; np++)
        bOff[np] = (uint32_t)((wn * 32 + np * 16 + qh * 8 + r8) * 128);

    float acc[4][4][4];
#pragma unroll
    for (int mt = 0; mt < 4; mt++)
#pragma unroll
        for (int ntl = 0; ntl < 4; ntl++)
#pragma unroll
            for (int j = 0; j < 4; j++) acc[mt][ntl][j] = 0.f;

    ISSUE_STAGE(0);
    ISSUE_STAGE(1);

    for (int ks = 0; ks < NK; ks++) {
        // 1) wait for stage ks: own cp.async groups + bulk mbarrier
        if (!mode) {
            if (ks < NK - 1) asm volatile("cp.async.wait_group 1;" ::: "memory");
            else             asm volatile("cp.async.wait_group 0;" ::: "memory");
        }
        MBARRIER_WAIT_PARITY(mb[ks % NSTAGE], (ks / NSTAGE) & 1);
        // 2) barrier: every thread's stage-ks copies are complete AND every
        //    thread finished consuming stage ks-1 -> reissue slot is free
        __syncthreads();
        // 3) refill slot (ks-1)%3 with stage ks+2
        if (ks + 2 < NK) ISSUE_STAGE(ks + 2);

        const uint32_t sA = suA + (uint32_t)((ks % NSTAGE) * STG_BYTES);
        const uint32_t sB = sA + 16384;

#pragma unroll
        for (int kk = 0; kk < 4; kk++) {
            const uint32_t xa = (uint32_t)(((kk * 2 + qh) ^ r8) << 4);
            const uint32_t xb = (uint32_t)(((kk * 2 + ql) ^ r8) << 4);
            uint32_t a[4][4], b[2][4];
#pragma unroll
            for (int mt = 0; mt < 4; mt++) ldsm4(a[mt], sA + aOff[mt] + xa);
#pragma unroll
            for (int np = 0; np < 2; np++) ldsm4(b[np], sB + bOff[np] + xb);
#pragma unroll
            for (int mt = 0; mt < 4; mt++)
#pragma unroll
                for (int ntl = 0; ntl < 4; ntl++)
                    mma_tf32(acc[mt][ntl], a[mt], &b[ntl >> 1][(ntl & 1) * 2]);
        }
    }

    // Epilogue
    if (mode == 0) {
        // write gelu+tf32 into k-chunk tiled g_hmid (chunk fixed per warp);
        // r&7 == tile-local&7 because rowStart is 128-aligned
        int chunk = (n0 >> 5) + wn;
#pragma unroll
        for (int mt = 0; mt < 4; mt++) {
#pragma unroll
            for (int i = 0; i < 2; i++) {
                int r = rowStart + wm * 64 + mt * 16 + g + i * 8;
                if (r >= rowEnd) continue;
                float* cb = g_hmid + ((size_t)chunk * TROWS + r) * 32;
#pragma unroll
                for (int ntl = 0; ntl < 4; ntl++) {
                    int cc = ntl * 8 + tig * 2;
                    float v0 = acc[mt][ntl][i * 2 + 0] + s_bias[wn * 32 + cc];
                    float v1 = acc[mt][ntl][i * 2 + 1] + s_bias[wn * 32 + cc + 1];
                    v0 = to_tf32(gelu_exact(v0));
                    v1 = to_tf32(gelu_exact(v1));
                    int idx = ((((cc >> 2) ^ (r & 7)) << 2) | (cc & 3));
                    *(float2*)(cb + idx) = make_float2(v0, v1);
                }
            }
        }
    } else {
#pragma unroll
        for (int mt = 0; mt < 4; mt++) {
#pragma unroll
            for (int i = 0; i < 2; i++) {
                int r = rowStart + wm * 64 + mt * 16 + g + i * 8;
                if (r >= rowEnd) continue;
                float* drow = g_y + (size_t)r * H_DIM + n0;
#pragma unroll
                for (int ntl = 0; ntl < 4; ntl++) {
                    int c = wn * 32 + ntl * 8 + tig * 2;
                    float v0 = acc[mt][ntl][i * 2 + 0] + s_bias[c];
                    float v1 = acc[mt][ntl][i * 2 + 1] + s_bias[c + 1];
                    *(float2*)(drow + c) = make_float2(v0, v1);
                }
            }
        }
    }
#undef ISSUE_STAGE
}

// ---------------------------------------------------------------------------
// Kernel 5: combine — out[t] = w0*y[pos0] + w1*y[pos1]
// ---------------------------------------------------------------------------
__global__ void combine_kernel(float* __restrict__ out) {
    int t = blockIdx.x;
    int p0 = g_slotPos[2 * t], p1 = g_slotPos[2 * t + 1];
    float w0 = g_wts[2 * t], w1 = g_wts[2 * t + 1];
    const float4* y0 = (const float4*)(g_y + (size_t)p0 * H_DIM);
    const float4* y1 = (const float4*)(g_y + (size_t)p1 * H_DIM);
    float4* o = (float4*)(out + (size_t)t * H_DIM);
    int i = threadIdx.x;
    float4 a = y0[i], b = y1[i];
    o[i] = make_float4(w0 * a.x + w1 * b.x, w0 * a.y + w1 * b.y,
                       w0 * a.z + w1 * b.z, w0 * a.w + w1 * b.w);
}

// ---------------------------------------------------------------------------
// Launch — moe_gemm(0) stays at kernel launch index 3 (ncu window)
// ---------------------------------------------------------------------------
extern "C" void kernel_launch(void* const* d_in, const int* in_sizes, int n_in,
                              void* d_out, int out_size) {
    const float* x  = (const float*)d_in[0];  // hidden_states [B,S,H]
    const float* gw = (const float*)d_in[1];  // gate_w [E,H]
    const float* w1 = (const float*)d_in[2];  // [E,H,I]
    const float* b1 = (const float*)d_in[3];  // [E,I]
    const float* w2 = (const float*)d_in[4];  // [E,I,H]
    const float* b2 = (const float*)d_in[5];  // [E,H]
    float* out = (float*)d_out;
    float* logits = out + ((size_t)out_size - (size_t)T_TOK * E_NUM);

    (void)cudaGetLastError();   // scrub any stale sticky error from env flake

    cudaFuncSetAttribute(moe_gemm, cudaFuncAttributeMaxDynamicSharedMemorySize, GEMM_SMEM);

    void* countsPtr = nullptr;
    cudaGetSymbolAddress(&countsPtr, g_counts);
    cudaMemsetAsync(countsPtr, 0, E_NUM * sizeof(int));         // memset node

    router_kernel<<<T_TOK / 8, 256>>>(x, gw, logits);           // k0
    plan_kernel<<<1, 32>>>();                                   // k1
    prep_kernel<<<dim3(96, 24, 17), dim3(32, 8)>>>(w1, w2);     // k2
    moe_gemm<<<dim3(I_DIM / BN, MAX_TILES), 256, GEMM_SMEM>>>(0, b1);  // k3 <- profiled
    moe_gemm<<<dim3(H_DIM / BN, MAX_TILES), 256, GEMM_SMEM>>>(1, b2);  // k4
    combine_kernel<<<T_TOK, 192>>>(out);                        // k5
}